// round 12
// baseline (speedup 1.0000x reference)
#include <cuda_runtime.h>
#include <cuda_fp16.h>
#include <math.h>
#include <stdint.h>

#define B_   8
#define M_   128
#define HID_ 256
#define NH_  8
#define D_   32

// ---------------- scratch (device globals: no allocations allowed) ----------
__device__ float g_q  [B_*M_*HID_];
__device__ float g_v  [B_*M_*HID_];
__device__ float g_nh [B_*M_*HID_];
__device__ float g_S  [B_*NH_*M_*M_];
__device__ float g_msg[B_*M_*M_*NH_];               // layout [(b,m,n), h]
__device__ float g_dm [B_*M_*M_];                   // mask * exp(-lam*dist)
__device__ unsigned short g_k16 [(long long)B_*M_*M_*HID_];   // fp16 k (67 MB)
__device__ unsigned short g_Wk16[HID_*HID_];
__device__ unsigned short g_We16[HID_*HID_];

// ---------------------------- helpers ---------------------------------------
__device__ __forceinline__ uint32_t smem_u32(const void* p) {
    uint32_t a;
    asm("{ .reg .u64 t; cvta.to.shared.u64 t, %1; cvt.u32.u64 %0, t; }" : "=r"(a) : "l"(p));
    return a;
}
__device__ __forceinline__ void cp_async16(uint32_t dst, const void* src) {
    asm volatile("cp.async.cg.shared.global [%0], [%1], 16;" :: "r"(dst), "l"(src));
}
__device__ __forceinline__ void ldsm_x4(uint32_t* r, uint32_t addr) {
    asm volatile("ldmatrix.sync.aligned.m8n8.x4.shared.b16 {%0,%1,%2,%3}, [%4];"
        : "=r"(r[0]), "=r"(r[1]), "=r"(r[2]), "=r"(r[3]) : "r"(addr));
}
__device__ __forceinline__ void mma16816(float* c, const uint32_t* a, const uint32_t* b) {
    asm volatile("mma.sync.aligned.m16n8k16.row.col.f32.f16.f16.f32 "
        "{%0,%1,%2,%3}, {%4,%5,%6,%7}, {%8,%9}, {%0,%1,%2,%3};"
        : "+f"(c[0]), "+f"(c[1]), "+f"(c[2]), "+f"(c[3])
        : "r"(a[0]), "r"(a[1]), "r"(a[2]), "r"(a[3]), "r"(b[0]), "r"(b[1]));
}
__device__ __forceinline__ float mishf(float x) {
    if (x > 20.0f) return x;
    float t = __expf(x);
    float u = t * (t + 2.0f);
    return x * __fdividef(u, u + 2.0f);
}

// ---------------------------------------------------------------------------
// HMMA GEMM: C[131072 x 256] = epi( A'[131072 x 256] @ W16^T + bias )
//   MODE 0 (k-proj):   A = fp32 edge -> cvt fp16; epi: +bias -> k16 (fp16)
//                      + FUSED SCORES: S[b,h,m,n] = scale * sum_col k*q
//   MODE 1 (edge-out): A = fp16 k scaled per (row, head) by msg_t;
//                      epi: +bias, mish, store fp32
// Tile: BM=128 x BN=256 x BK=64 (4 iters). 256 threads (8 warps, 2x4),
// warp tile 64x64. B: 3-stage cp.async pipeline. A: LDG->reg->STS dbl buffer.
// Smem rows = 64 halves + 16B pad = 144B (conflict-free ldsm).
// ---------------------------------------------------------------------------
#define LDT 144           // bytes per padded smem row (64 halves + pad)
#define OFF_SCALE 0       // 1024 floats (MODE 1)
#define OFF_BIAS  4096    // 256 floats
#define OFF_QS    5120    // 256 floats (MODE 0)
#define OFF_SRED  6144    // 128*8 floats (MODE 0)
#define OFF_T     10240
#define ASZ (128*LDT)     // 18432
#define BSZ (256*LDT)     // 36864
#define SMEM_MMA (OFF_T + 2*ASZ + 3*BSZ)   // 157696

template<int MODE>
__global__ __launch_bounds__(256) void mma_gemm(
    const void* __restrict__ Asrc, const unsigned short* __restrict__ W16v,
    const float* __restrict__ bias, void* __restrict__ Cout,
    const float* __restrict__ msg_t,
    const float* __restrict__ qglob, float* __restrict__ Sglob)
{
    extern __shared__ __align__(128) char smem[];
    float* sclS  = (float*)(smem + OFF_SCALE);
    float* biasS = (float*)(smem + OFF_BIAS);
    float* qs    = (float*)(smem + OFF_QS);
    float* sred  = (float*)(smem + OFF_SRED);
    const uint32_t sb = smem_u32(smem);
    const uint32_t sA0 = sb + OFF_T;
    const uint32_t sA1 = sA0 + ASZ;
    const uint32_t sB0 = sA1 + ASZ;
    const uint32_t sB1 = sB0 + BSZ;
    const uint32_t sB2 = sB1 + BSZ;

    const int tid  = threadIdx.x;
    const int lane = tid & 31, warp = tid >> 5;      // warp 0..7
    const int wm = warp >> 2, wn = warp & 3;         // 2 x 4
    const long long rb = (long long)blockIdx.x * 128;
    const __half* W16 = (const __half*)W16v;

    biasS[tid] = bias[tid];
    if (MODE == 1) {
        // msg_t layout [(b,m,n), h]: rows rb..rb+127 x 8 heads, contiguous
        const float4* ms = (const float4*)(msg_t + rb*8);
        ((float4*)sclS)[tid] = ms[tid];
    } else {
        // this CTA covers rows (b, m, n=0..127): (b, m) fixed
        int bq = (int)(rb >> 14), mq = (int)((rb >> 7) & 127);
        qs[tid] = qglob[((long long)bq*128 + mq)*256 + tid];
    }
    __syncthreads();

    // A loader: thread -> (row = tid>>1, khalf = tid&1), 32 elems (= 64B fp16)
    const int arow  = tid >> 1;
    const int khalf = tid & 1;

    float4 fa[8];   // MODE 0 staging: 32 fp32
    uint4  ua[4];   // MODE 1 staging: 32 fp16 = 64 B

#define LD_A(it) do {                                                          \
    if (MODE == 0) {                                                           \
        const float4* src = (const float4*)((const float*)Asrc                 \
            + (rb + arow)*256 + (it)*64 + khalf*32);                           \
        fa[0]=src[0]; fa[1]=src[1]; fa[2]=src[2]; fa[3]=src[3];                \
        fa[4]=src[4]; fa[5]=src[5]; fa[6]=src[6]; fa[7]=src[7];                \
    } else {                                                                   \
        const uint4* src = (const uint4*)((const __half*)Asrc                  \
            + (rb + arow)*256 + (it)*64 + khalf*32);                           \
        ua[0]=src[0]; ua[1]=src[1]; ua[2]=src[2]; ua[3]=src[3];                \
    } } while (0)

#define ST_A(it, sA) do {                                                      \
    uint32_t dst = (sA) + arow*LDT + khalf*64;                                 \
    if (MODE == 0) {                                                           \
        _Pragma("unroll")                                                      \
        for (int j = 0; j < 2; j++) {                                          \
            __half2 h0 = __floats2half2_rn(fa[j*4+0].x, fa[j*4+0].y);          \
            __half2 h1 = __floats2half2_rn(fa[j*4+0].z, fa[j*4+0].w);          \
            __half2 h2 = __floats2half2_rn(fa[j*4+1].x, fa[j*4+1].y);          \
            __half2 h3 = __floats2half2_rn(fa[j*4+1].z, fa[j*4+1].w);          \
            __half2 h4 = __floats2half2_rn(fa[j*4+2].x, fa[j*4+2].y);          \
            __half2 h5 = __floats2half2_rn(fa[j*4+2].z, fa[j*4+2].w);          \
            __half2 h6 = __floats2half2_rn(fa[j*4+3].x, fa[j*4+3].y);          \
            __half2 h7 = __floats2half2_rn(fa[j*4+3].z, fa[j*4+3].w);          \
            asm volatile("st.shared.v4.b32 [%0], {%1,%2,%3,%4};"               \
                :: "r"(dst + j*32),                                            \
                   "r"(*(uint32_t*)&h0), "r"(*(uint32_t*)&h1),                 \
                   "r"(*(uint32_t*)&h2), "r"(*(uint32_t*)&h3));                \
            asm volatile("st.shared.v4.b32 [%0], {%1,%2,%3,%4};"               \
                :: "r"(dst + j*32 + 16),                                       \
                   "r"(*(uint32_t*)&h4), "r"(*(uint32_t*)&h5),                 \
                   "r"(*(uint32_t*)&h6), "r"(*(uint32_t*)&h7));                \
        }                                                                      \
    } else {                                                                   \
        __half2 s2 = __float2half2_rn(sclS[arow*8 + (it)*2 + khalf]);          \
        _Pragma("unroll")                                                      \
        for (int j = 0; j < 4; j++) {                                          \
            uint4 t0 = ua[j]; __half2* hp = (__half2*)&t0;                     \
            hp[0]=__hmul2(hp[0],s2); hp[1]=__hmul2(hp[1],s2);                  \
            hp[2]=__hmul2(hp[2],s2); hp[3]=__hmul2(hp[3],s2);                  \
            asm volatile("st.shared.v4.b32 [%0], {%1,%2,%3,%4};"               \
                :: "r"(dst + j*16),                                            \
                   "r"(t0.x), "r"(t0.y), "r"(t0.z), "r"(t0.w));                \
        }                                                                      \
    } } while (0)

#define CP_B(it, sB) do {                                                      \
    _Pragma("unroll")                                                          \
    for (int j = 0; j < 8; j++) {                                              \
        int idx = tid + j*256;                                                 \
        int n = idx >> 3, seg = idx & 7;                                       \
        cp_async16((sB) + n*LDT + seg*16, W16 + n*256 + (it)*64 + seg*8);      \
    } } while (0)

    float c[4][8][4];
    #pragma unroll
    for (int mt = 0; mt < 4; mt++)
        #pragma unroll
        for (int nt = 0; nt < 8; nt++)
            #pragma unroll
            for (int j = 0; j < 4; j++) c[mt][nt][j] = 0.0f;

    // ldmatrix per-lane address components
    const uint32_t a_off = (uint32_t)((wm*64 + (lane & 15))*LDT + (lane >> 4)*16);
    const uint32_t b_off = (uint32_t)((wn*64 + (lane & 7) + (lane >> 4)*8)*LDT
                                      + ((lane >> 3) & 1)*16);

    // ---------------- prologue: prime A(0) and B(0), B(1)
    LD_A(0);
    CP_B(0, sB0);
    asm volatile("cp.async.commit_group;" ::: "memory");
    CP_B(1, sB1);
    asm volatile("cp.async.commit_group;" ::: "memory");
    ST_A(0, sA0);
    asm volatile("cp.async.wait_group 1;" ::: "memory");   // B(0) arrived
    __syncthreads();

    uint32_t sAcur = sA0, sAnxt = sA1;
    uint32_t sBcur = sB0, sBnxt = sB1, sBnn = sB2;

    // ---------------- main loop: 4 k-iters of 64
    #pragma unroll 1
    for (int it = 0; it < 4; it++) {
        if (it < 3) LD_A(it + 1);
        if (it < 2) {
            CP_B(it + 2, sBnn);
            asm volatile("cp.async.commit_group;" ::: "memory");
        }

        #pragma unroll
        for (int ks = 0; ks < 4; ks++) {
            uint32_t a[4][4], bfr[4][4];
            const uint32_t ab = sAcur + a_off + ks*32;
            #pragma unroll
            for (int mt = 0; mt < 4; mt++) ldsm_x4(a[mt], ab + mt*16*LDT);
            const uint32_t bb = sBcur + b_off + ks*32;
            #pragma unroll
            for (int ntp = 0; ntp < 4; ntp++) ldsm_x4(bfr[ntp], bb + ntp*16*LDT);
            #pragma unroll
            for (int mt = 0; mt < 4; mt++)
                #pragma unroll
                for (int nt = 0; nt < 8; nt++)
                    mma16816(c[mt][nt], a[mt], &bfr[nt >> 1][(nt & 1)*2]);
        }

        if (it < 3) ST_A(it + 1, sAnxt);
        if (it < 2) {
            asm volatile("cp.async.wait_group 1;" ::: "memory"); // B(it+1) done
        } else if (it == 2) {
            asm volatile("cp.async.wait_group 0;" ::: "memory"); // B(3) done
        }
        __syncthreads();

        uint32_t t = sAcur; sAcur = sAnxt; sAnxt = t;
        t = sBcur; sBcur = sBnxt; sBnxt = sBnn; sBnn = t;
    }

    // ---------------- epilogue
    const int mrow = lane >> 2;
    const int ncol = (lane & 3)*2;
    float p[2][8];
    if (MODE == 0) {
        #pragma unroll
        for (int hl = 0; hl < 2; hl++)
            #pragma unroll
            for (int rs = 0; rs < 8; rs++) p[hl][rs] = 0.0f;
    }

    #pragma unroll
    for (int mt = 0; mt < 4; mt++) {
        #pragma unroll
        for (int nt = 0; nt < 8; nt++) {
            const int m = wm*64 + mt*16 + mrow;
            const int n = wn*64 + nt*8 + ncol;
            const float b0 = biasS[n], b1 = biasS[n+1];
            float* cc = c[mt][nt];
            if (MODE == 0) {
                float v0 = cc[0] + b0, v1 = cc[1] + b1;
                float v2 = cc[2] + b0, v3 = cc[3] + b1;
                __half2 h0 = __floats2half2_rn(v0, v1);
                __half2 h1 = __floats2half2_rn(v2, v3);
                unsigned short* o = (unsigned short*)Cout;
                *(uint32_t*)(o + (rb + m)*256 + n)     = *(uint32_t*)&h0;
                *(uint32_t*)(o + (rb + m + 8)*256 + n) = *(uint32_t*)&h1;
                // fused scores partials: head = n/32, rows are n-positions
                const int hl = nt >> 2;
                const float q0 = qs[n], q1 = qs[n+1];
                p[hl][mt*2+0] += v0*q0 + v1*q1;
                p[hl][mt*2+1] += v2*q0 + v3*q1;
            } else {
                float* o = (float*)Cout;
                float2 o0 = { mishf(cc[0] + b0), mishf(cc[1] + b1) };
                float2 o1 = { mishf(cc[2] + b0), mishf(cc[3] + b1) };
                *(float2*)(o + (rb + m)*256 + n)     = o0;
                *(float2*)(o + (rb + m + 8)*256 + n) = o1;
            }
        }
    }

    if (MODE == 0) {
        // reduce partials over the 4 lanes sharing a row (lane^1, lane^2)
        #pragma unroll
        for (int o = 1; o <= 2; o <<= 1)
            #pragma unroll
            for (int hl = 0; hl < 2; hl++)
                #pragma unroll
                for (int rs = 0; rs < 8; rs++)
                    p[hl][rs] += __shfl_xor_sync(0xffffffffu, p[hl][rs], o);
        if ((lane & 3) == 0) {
            #pragma unroll
            for (int mt = 0; mt < 4; mt++)
                #pragma unroll
                for (int half = 0; half < 2; half++)
                    #pragma unroll
                    for (int hl = 0; hl < 2; hl++) {
                        int nloc = wm*64 + mt*16 + mrow + half*8;
                        sred[nloc*8 + wn*2 + hl] = p[hl][mt*2 + half];
                    }
        }
        __syncthreads();
        const int bq = (int)(rb >> 14), mq = (int)((rb >> 7) & 127);
        const float scale = 0.17677669529663687f;   // 1/sqrt(32)
        #pragma unroll
        for (int i = tid; i < 1024; i += 256) {
            int n = i >> 3, h = i & 7;
            Sglob[((((long long)bq*8 + h)*128 + mq)*128) + n] = sred[n*8 + h]*scale;
        }
    }
#undef LD_A
#undef ST_A
#undef CP_B
}

// ---------------------------------------------------------------------------
// W fp32 -> fp16 prep
// ---------------------------------------------------------------------------
__global__ void prep_w16(const float* __restrict__ Wk, const float* __restrict__ We,
                         unsigned short* __restrict__ Wk16, unsigned short* __restrict__ We16)
{
    int i = blockIdx.x * 256 + threadIdx.x;
    __half a = __float2half(Wk[i]);
    __half b = __float2half(We[i]);
    Wk16[i] = *(unsigned short*)&a;
    We16[i] = *(unsigned short*)&b;
}

// ---------------------------------------------------------------------------
// dm[b,m,n] = mask[b,n] ? exp(-lam*dist[b,m,n]) : 0   (one-time, dedup x8 heads)
// ---------------------------------------------------------------------------
__global__ void dm_kernel(const float* __restrict__ dist, const float* __restrict__ mask,
                          const float* __restrict__ lam, float* __restrict__ dm)
{
    int idx = blockIdx.x * 256 + threadIdx.x;   // over B*M*M = 131072
    int b = idx >> 14, n = idx & 127;
    float mv = mask[b*128 + n];
    dm[idx] = (mv != 0.0f) ? __expf(-lam[0]*dist[idx]) : 0.0f;
}

// ---------------------------------------------------------------------------
// small SIMT GEMM body (q/v/node_out): 64x64x16 tile, fp32
// ---------------------------------------------------------------------------
template<int MODE>   // 0 = identity, 1 = mish
__device__ __forceinline__ void gemm_body(
    const float* __restrict__ A, const float* __restrict__ W,
    const float* __restrict__ bias, float* __restrict__ C,
    int bx, int by)
{
    __shared__ float As[16][64];
    __shared__ float Ws[16][64];
    const int tid = threadIdx.x;
    const long long rb = (long long)by * 64;
    const int cb = bx * 64;
    const int lr = tid >> 2, lk = (tid & 3) << 2;
    const int tr = tid & 15, tc = tid >> 4;
    float acc[4][4] = {};
    for (int k0 = 0; k0 < 256; k0 += 16) {
        float4 av = *reinterpret_cast<const float4*>(&A[(rb + lr)*256 + k0 + lk]);
        As[lk+0][lr] = av.x; As[lk+1][lr] = av.y; As[lk+2][lr] = av.z; As[lk+3][lr] = av.w;
        float4 wv = *reinterpret_cast<const float4*>(&W[(long long)(cb + lr)*256 + k0 + lk]);
        Ws[lk+0][lr] = wv.x; Ws[lk+1][lr] = wv.y; Ws[lk+2][lr] = wv.z; Ws[lk+3][lr] = wv.w;
        __syncthreads();
        #pragma unroll
        for (int kk = 0; kk < 16; kk++) {
            float4 a4 = *reinterpret_cast<const float4*>(&As[kk][tr*4]);
            float4 w4 = *reinterpret_cast<const float4*>(&Ws[kk][tc*4]);
            float a[4] = {a4.x, a4.y, a4.z, a4.w};
            float w[4] = {w4.x, w4.y, w4.z, w4.w};
            #pragma unroll
            for (int i = 0; i < 4; i++)
                #pragma unroll
                for (int j = 0; j < 4; j++) acc[i][j] += a[i]*w[j];
        }
        __syncthreads();
    }
    #pragma unroll
    for (int i = 0; i < 4; i++) {
        long long row = rb + tr*4 + i;
        #pragma unroll
        for (int j = 0; j < 4; j++) {
            int col = cb + tc*4 + j;
            float v = acc[i][j] + bias[col];
            if (MODE == 1) v = mishf(v);
            C[row*256 + col] = v;
        }
    }
}

__global__ __launch_bounds__(256) void proj_qv(
    const float* __restrict__ node,
    const float* __restrict__ Wq, const float* __restrict__ bq,
    const float* __restrict__ Wv, const float* __restrict__ bv,
    float* __restrict__ q, float* __restrict__ v)
{
    if (blockIdx.z == 0) gemm_body<0>(node, Wq, bq, q, blockIdx.x, blockIdx.y);
    else                 gemm_body<0>(node, Wv, bv, v, blockIdx.x, blockIdx.y);
}

__global__ __launch_bounds__(256) void node_out_gemm(
    const float* __restrict__ nh, const float* __restrict__ Wn,
    const float* __restrict__ bn, float* __restrict__ C)
{
    gemm_body<1>(nh, Wn, bn, C, blockIdx.x, blockIdx.y);
}

// ---------------------------------------------------------------------------
// softmax / message / node_hidden v2.
// grid (4 m-chunks, 64 bh); 256 threads. Per CTA: 32 rows of one (b,h).
// E matrices computed in-place (1 expf per cell); dm precomputed.
// msg written head-innermost: msg_t[(b,m,n), h].
// ---------------------------------------------------------------------------
#define SROW_ST 129
#define SCOL_ST 33
#define VS_ST   36
#define SMEM_MSG ((32*SROW_ST + 128*SCOL_ST + 128*VS_ST) * 4)   // 51840 B

__global__ __launch_bounds__(256) void message_kernel(
    const float* __restrict__ S, const float* __restrict__ v,
    const float* __restrict__ dm, const float* __restrict__ mask,
    float* __restrict__ msg_t, float* __restrict__ nh)
{
    extern __shared__ float sm[];
    float* Srow = sm;                          // 32 x 129 (rows m0..m0+31)
    float* Scol = Srow + 32*SROW_ST;           // 128 x 33 (S[:, m0..m0+31])
    float* vs   = Scol + 128*SCOL_ST;          // 128 x 36
    __shared__ float msk[128];
    __shared__ float rmaxS[32], rsumS[32], cmaxS[32], csumS[32];

    const int bh = blockIdx.y;
    const int b = bh >> 3, h = bh & 7;
    const int m0 = blockIdx.x * 32;
    const int tid = threadIdx.x;

    const float* Sg = S + (long long)bh*128*128;
    #pragma unroll 2
    for (int idx = tid; idx < 32*128; idx += 256)
        Srow[(idx >> 7)*SROW_ST + (idx & 127)] = Sg[(m0 + (idx >> 7))*128 + (idx & 127)];
    #pragma unroll 2
    for (int idx = tid; idx < 128*32; idx += 256)
        Scol[(idx >> 5)*SCOL_ST + (idx & 31)] = Sg[(idx >> 5)*128 + m0 + (idx & 31)];
    #pragma unroll 2
    for (int idx = tid; idx < 128*32; idx += 256)
        vs[(idx >> 5)*VS_ST + (idx & 31)] = v[((b*128 + (idx >> 5))*256) + h*32 + (idx & 31)];
    if (tid < 128) msk[tid] = mask[b*128 + tid];
    __syncthreads();

    const int r  = tid >> 3;       // 0..31 : local row (or local col)
    const int sl = tid & 7;        // 8 lanes cooperate per row

    // ---- pass A: maxes (row r of chunk; column m0+r)
    float rmax = -1e30f, cmax = -1e30f;
    #pragma unroll 4
    for (int i = 0; i < 16; i++) {
        int n = sl + i*8;
        if (msk[n] != 0.0f) {
            rmax = fmaxf(rmax, Srow[r*SROW_ST + n]);
            cmax = fmaxf(cmax, Scol[n*SCOL_ST + r]);
        }
    }
    #pragma unroll
    for (int o = 1; o <= 4; o <<= 1) {
        rmax = fmaxf(rmax, __shfl_xor_sync(0xffffffffu, rmax, o));
        cmax = fmaxf(cmax, __shfl_xor_sync(0xffffffffu, cmax, o));
    }
    if (sl == 0) { rmaxS[r] = rmax; cmaxS[r] = cmax; }
    __syncthreads();

    // ---- pass B: E = exp(S - max) in place (masked -> 0), sums
    rmax = rmaxS[r]; cmax = cmaxS[r];
    float rsum = 0.0f, csum = 0.0f;
    #pragma unroll 4
    for (int i = 0; i < 16; i++) {
        int n = sl + i*8;
        float er = 0.0f, ec = 0.0f;
        if (msk[n] != 0.0f) {
            er = __expf(Srow[r*SROW_ST + n] - rmax);
            ec = __expf(Scol[n*SCOL_ST + r] - cmax);
        }
        Srow[r*SROW_ST + n] = er;  rsum += er;
        Scol[n*SCOL_ST + r] = ec;  csum += ec;
    }
    #pragma unroll
    for (int o = 1; o <= 4; o <<= 1) {
        rsum += __shfl_xor_sync(0xffffffffu, rsum, o);
        csum += __shfl_xor_sync(0xffffffffu, csum, o);
    }
    if (sl == 0) { rsumS[r] = 1.0f / rsum; csumS[r] = 1.0f / csum; }
    __syncthreads();

    // ---- pass C: msg (overwrite Srow in place), write msg_t global
    const float inv_rs = rsumS[r], inv_cs = csumS[r];
    const int mglob = m0 + r;
    const float* dmr = dm + ((long long)b*128 + mglob)*128;
    float* mtr = msg_t + (((long long)b*128 + mglob)*128)*8 + h;
    #pragma unroll 4
    for (int i = 0; i < 16; i++) {
        int n = sl + i*8;
        float eo = Srow[r*SROW_ST + n] * inv_rs;
        float ei = Scol[n*SCOL_ST + r] * inv_cs;
        float t  = (n == mglob) ? ei : (eo + ei);
        float mv = t * dmr[n];
        Srow[r*SROW_ST + n] = mv;
        mtr[n*8] = mv;
    }
    __syncthreads();

    // ---- pass D: node_hidden partial rows (complete: full n-range here)
    const int d0 = sl*4;
    float a0 = 0.0f, a1 = 0.0f, a2 = 0.0f, a3 = 0.0f;
    #pragma unroll 4
    for (int n = 0; n < 128; n++) {
        float mv = Srow[r*SROW_ST + n];
        float4 vv = *(const float4*)&vs[n*VS_ST + d0];
        a0 += mv*vv.x; a1 += mv*vv.y; a2 += mv*vv.z; a3 += mv*vv.w;
    }
    float* nhr = nh + ((long long)(b*128 + mglob))*256 + h*32 + d0;
    *(float4*)nhr = make_float4(a0, a1, a2, a3);
}

// ---------------------------------------------------------------------------
extern "C" void kernel_launch(void* const* d_in, const int* in_sizes, int n_in,
                              void* d_out, int out_size)
{
    const float* node = (const float*)d_in[0];
    const float* edge = (const float*)d_in[1];
    const float* dist = (const float*)d_in[2];
    const float* mask = (const float*)d_in[3];
    const float* lam  = (const float*)d_in[4];
    const float* Wq   = (const float*)d_in[5];
    const float* bq   = (const float*)d_in[6];
    const float* Wk   = (const float*)d_in[7];
    const float* bk   = (const float*)d_in[8];
    const float* Wv   = (const float*)d_in[9];
    const float* bv   = (const float*)d_in[10];
    const float* Wn   = (const float*)d_in[11];
    const float* bn   = (const float*)d_in[12];
    const float* We   = (const float*)d_in[13];
    const float* be   = (const float*)d_in[14];

    float* out = (float*)d_out;
    float* node_out = out;
    float* edge_out = out + B_*M_*HID_;

    float *q, *v, *S, *msg, *nh, *dm;
    unsigned short *k16, *Wk16, *We16;
    cudaGetSymbolAddress((void**)&q,    g_q);
    cudaGetSymbolAddress((void**)&v,    g_v);
    cudaGetSymbolAddress((void**)&S,    g_S);
    cudaGetSymbolAddress((void**)&msg,  g_msg);
    cudaGetSymbolAddress((void**)&nh,   g_nh);
    cudaGetSymbolAddress((void**)&dm,   g_dm);
    cudaGetSymbolAddress((void**)&k16,  g_k16);
    cudaGetSymbolAddress((void**)&Wk16, g_Wk16);
    cudaGetSymbolAddress((void**)&We16, g_We16);

    cudaFuncSetAttribute(message_kernel,
                         cudaFuncAttributeMaxDynamicSharedMemorySize, SMEM_MSG);
    cudaFuncSetAttribute(mma_gemm<0>,
                         cudaFuncAttributeMaxDynamicSharedMemorySize, SMEM_MMA);
    cudaFuncSetAttribute(mma_gemm<1>,
                         cudaFuncAttributeMaxDynamicSharedMemorySize, SMEM_MMA);

    prep_w16<<<256, 256>>>(Wk, We, Wk16, We16);
    dm_kernel<<<512, 256>>>(dist, mask, lam, dm);
    proj_qv<<<dim3(4, 16, 2), 256>>>(node, Wq, bq, Wv, bv, q, v);
    mma_gemm<0><<<1024, 256, SMEM_MMA>>>(edge, Wk16, bk, k16, nullptr, q, S);
    message_kernel<<<dim3(4, 64), 256, SMEM_MSG>>>(S, v, dm, mask, msg, nh);
    mma_gemm<1><<<1024, 256, SMEM_MMA>>>(k16, We16, be, edge_out, msg, nullptr, nullptr);
    node_out_gemm<<<dim3(4, 16), 256>>>(nh, Wn, bn, node_out);
}